// round 7
// baseline (speedup 1.0000x reference)
#include <cuda_runtime.h>
#include <cstdint>

#define S_ 512
#define L_ 256
#define H_ 768
#define P_ 8
#define K_ 8
#define H4_ 192                 // float4 per row
#define ROWB_ 3072              // bytes per row
#define BATCH_ 12               // rows per pipeline stage
#define STAGEB_ (BATCH_ * ROWB_)    // 36864
#define MAXE_ 192               // worst-case entries (3*8*8)
#define THREADS_ 192

// dynamic smem layout
#define OFF_ROWS   0
#define OFF_MBAR   (2 * STAGEB_)            // 73728, two 8B mbarriers
#define OFF_EIDX   (OFF_MBAR + 16)          // 73744, 192 ints
#define OFF_EW     (OFF_EIDX + MAXE_ * 4)   // 74512, 192 floats
#define OFF_EROLE  (OFF_EW   + MAXE_ * 4)   // 75280, 192 ints
#define SMEM_TOTAL (OFF_EROLE + MAXE_ * 4)  // 76048

extern __shared__ __align__(16) unsigned char dsm[];

__device__ __forceinline__ uint32_t smem_u32(const void* p) {
    uint32_t a;
    asm("{ .reg .u64 t; cvta.to.shared.u64 t, %1; cvt.u32.u64 %0, t; }" : "=r"(a) : "l"(p));
    return a;
}

#define MBAR_INIT(addr, cnt) \
    asm volatile("mbarrier.init.shared.b64 [%0], %1;" :: "r"(addr), "r"(cnt) : "memory")
#define MBAR_EXPECT_TX(addr, bytes) \
    asm volatile("mbarrier.arrive.expect_tx.shared.b64 _, [%0], %1;" :: "r"(addr), "r"(bytes) : "memory")
#define BULK_CP(dst, src, bytes, mbar) \
    asm volatile("cp.async.bulk.shared::cta.global.mbarrier::complete_tx::bytes [%0], [%1], %2, [%3];" \
        :: "r"(dst), "l"(src), "r"(bytes), "r"(mbar) : "memory")

__device__ __forceinline__ void mbar_wait(uint32_t addr, uint32_t parity) {
    uint32_t done;
    asm volatile(
        "{\n\t.reg .pred p;\n\t"
        "mbarrier.try_wait.parity.acquire.cta.shared::cta.b64 p, [%1], %2;\n\t"
        "selp.b32 %0, 1, 0, p;\n\t}"
        : "=r"(done) : "r"(addr), "r"(parity) : "memory");
    while (!done) {
        asm volatile(
            "{\n\t.reg .pred p;\n\t"
            "mbarrier.try_wait.parity.acquire.cta.shared::cta.b64 p, [%1], %2, 0x989680;\n\t"
            "selp.b32 %0, 1, 0, p;\n\t}"
            : "=r"(done) : "r"(addr), "r"(parity) : "memory");
    }
}

__global__ __launch_bounds__(THREADS_, 1)
void srl_pool_kernel(const float* __restrict__ emb,
                     const int* __restrict__ idxV,  const int* __restrict__ mV,
                     const int* __restrict__ idxA0, const int* __restrict__ mA0,
                     const int* __restrict__ idxA1, const int* __restrict__ mA1,
                     const int* __restrict__ pred,
                     float* __restrict__ out)
{
    const int s   = blockIdx.x;
    const int tid = threadIdx.x;

    int*   e_idx  = reinterpret_cast<int*>(dsm + OFF_EIDX);
    float* e_w    = reinterpret_cast<float*>(dsm + OFF_EW);
    int*   e_role = reinterpret_cast<int*>(dsm + OFF_EROLE);
    const uint32_t mbar_base = smem_u32(dsm) + OFF_MBAR;

    __shared__ int s_nct;

    if (tid == 0) {
        MBAR_INIT(mbar_base + 0, 1);
        MBAR_INIT(mbar_base + 8, 1);
    }

    // ---------- Phase 1: 24-lane warp-scan compaction (role-major order) ----------
    if (tid < 3 * P_) {
        const unsigned FULL = 0x00FFFFFFu;
        const int role = tid >> 3;
        const int p    = tid & 7;
        const int* __restrict__ idx =
            (role == 0) ? idxV : (role == 1) ? idxA0 : idxA1;
        const int* __restrict__ msk =
            (role == 0) ? mV : (role == 1) ? mA0 : mA1;

        const int base = (s * P_ + p) * K_;
        int4 iv0 = *reinterpret_cast<const int4*>(idx + base);
        int4 iv1 = *reinterpret_cast<const int4*>(idx + base + 4);
        int4 mv0 = *reinterpret_cast<const int4*>(msk + base);
        int4 mv1 = *reinterpret_cast<const int4*>(msk + base + 4);
        int4 pv0 = *reinterpret_cast<const int4*>(pred + s * P_);
        int4 pv1 = *reinterpret_cast<const int4*>(pred + s * P_ + 4);

        int li[K_] = { iv0.x, iv0.y, iv0.z, iv0.w, iv1.x, iv1.y, iv1.z, iv1.w };
        int lm[K_] = { mv0.x, mv0.y, mv0.z, mv0.w, mv1.x, mv1.y, mv1.z, mv1.w };

        int lv[K_];
        int cnt = 0;
        #pragma unroll
        for (int k = 0; k < K_; k++) {
            int v = (lm[k] != 0) & (li[k] < L_) & (li[k] >= 0);
            li[k] = min(max(li[k], 0), L_ - 1);
            lv[k] = v;
            cnt  += v;
        }

        int pown  = (p < 4) ? ((const int*)&pv0)[p] : ((const int*)&pv1)[p - 4];
        int npred = (pv0.x != 0) + (pv0.y != 0) + (pv0.z != 0) + (pv0.w != 0)
                  + (pv1.x != 0) + (pv1.y != 0) + (pv1.z != 0) + (pv1.w != 0);

        int take = (pown != 0 && cnt > 0 && npred > 0);
        float w  = take ? 1.0f / ((float)cnt * (float)npred) : 0.0f;
        int eff  = take ? cnt : 0;

        // Inclusive scan over all 24 lanes (global, role-major positions).
        int off = eff;
        #pragma unroll
        for (int d = 1; d < 32; d <<= 1) {
            int y = __shfl_up_sync(FULL, off, d);
            if (tid >= d) off += y;
        }
        int pos = off - eff;

        if (take) {
            #pragma unroll
            for (int k = 0; k < K_; k++) {
                if (lv[k]) {
                    e_idx[pos]  = li[k];
                    e_w[pos]    = w;
                    e_role[pos] = role;
                    pos++;
                }
            }
        }
        if (tid == 23) s_nct = off;
    }
    __syncthreads();

    const int nct = s_nct;
    const int nb  = (nct + BATCH_ - 1) / BATCH_;
    const float* __restrict__ srow = emb + (size_t)s * L_ * H_;
    const uint32_t rows_base = smem_u32(dsm);

    // Producer: issue a whole batch of row copies into a stage.
    #define ISSUE(B) do {                                                      \
        int st  = (B) & 1;                                                     \
        int beg = (B) * BATCH_;                                                \
        int bcnt = min(BATCH_, nct - beg);                                     \
        MBAR_EXPECT_TX(mbar_base + st * 8, (uint32_t)(bcnt * ROWB_));          \
        for (int k = 0; k < bcnt; k++) {                                       \
            const void* src = srow + (size_t)e_idx[beg + k] * H_;              \
            uint32_t dst = rows_base + st * STAGEB_ + k * ROWB_;               \
            BULK_CP(dst, src, (uint32_t)ROWB_, mbar_base + st * 8);            \
        }                                                                      \
    } while (0)

    if (tid == 0) {
        if (nb > 0) ISSUE(0);
        if (nb > 1) ISSUE(1);
    }

    float4 a0 = make_float4(0.f, 0.f, 0.f, 0.f);
    float4 a1 = a0, a2 = a0;

    for (int b = 0; b < nb; b++) {
        const int st = b & 1;
        const int ph = (b >> 1) & 1;
        mbar_wait(mbar_base + st * 8, (uint32_t)ph);

        const int beg  = b * BATCH_;
        const int bcnt = min(BATCH_, nct - beg);
        const float4* __restrict__ vbase =
            reinterpret_cast<const float4*>(dsm + st * STAGEB_) + tid;

        for (int k = 0; k < bcnt; k++) {
            float  w = e_w[beg + k];
            int    r = e_role[beg + k];
            float4 v = vbase[k * H4_];
            if (r == 0) {
                a0.x += w * v.x; a0.y += w * v.y; a0.z += w * v.z; a0.w += w * v.w;
            } else if (r == 1) {
                a1.x += w * v.x; a1.y += w * v.y; a1.z += w * v.z; a1.w += w * v.w;
            } else {
                a2.x += w * v.x; a2.y += w * v.y; a2.z += w * v.z; a2.w += w * v.w;
            }
        }

        __syncthreads();                       // stage fully consumed
        if (tid == 0 && b + 2 < nb) ISSUE(b + 2);
    }
    #undef ISSUE

    float4* __restrict__ out4 = reinterpret_cast<float4*>(out);
    out4[((size_t)0 * S_ + s) * H4_ + tid] = a0;
    out4[((size_t)1 * S_ + s) * H4_ + tid] = a1;
    out4[((size_t)2 * S_ + s) * H4_ + tid] = a2;
}

extern "C" void kernel_launch(void* const* d_in, const int* in_sizes, int n_in,
                              void* d_out, int out_size)
{
    const float* emb   = (const float*)d_in[0];
    const int*   idxV  = (const int*)d_in[1];
    const int*   mV    = (const int*)d_in[2];
    const int*   idxA0 = (const int*)d_in[3];
    const int*   mA0   = (const int*)d_in[4];
    const int*   idxA1 = (const int*)d_in[5];
    const int*   mA1   = (const int*)d_in[6];
    const int*   pred  = (const int*)d_in[7];
    float* out = (float*)d_out;

    static int attr_set = 0;
    if (!attr_set) {
        cudaFuncSetAttribute(srl_pool_kernel,
                             cudaFuncAttributeMaxDynamicSharedMemorySize, SMEM_TOTAL);
        attr_set = 1;
    }
    srl_pool_kernel<<<S_, THREADS_, SMEM_TOTAL>>>(emb, idxV, mV, idxA0, mA0,
                                                  idxA1, mA1, pred, out);
}